// round 6
// baseline (speedup 1.0000x reference)
#include <cuda_runtime.h>
#include <cuda_bf16.h>
#include <float.h>

#define NEXP 64
#define TPB  256

// Rare exact path: faithful reproduction of the reference fp32 sequence
// (sqrt logits + softmax-tie band). __noinline__ + partial unroll so it never
// inflates the main kernel's register count (R3 lesson: inlining -> 255 regs).
__device__ __noinline__ int exact_argmax(float px, float py, float pz,
                                         const float4* __restrict__ sc)
{
    float m = -FLT_MAX;
    #pragma unroll 4
    for (int e = 0; e < NEXP; e++) {
        float4 c = sc[e];
        float dx = __fsub_rn(px, c.x);
        float dy = __fsub_rn(py, c.y);
        float dz = __fsub_rn(pz, c.z);
        float d2 = __fadd_rn(__fadd_rn(__fmul_rn(dx, dx), __fmul_rn(dy, dy)),
                             __fmul_rn(dz, dz));
        float dist = __fsqrt_rn(__fadd_rn(d2, 1e-12f));
        float li   = __fmul_rn(10.0f, __fsub_rn(c.w, dist));
        if (li > m) m = li;
    }
    // softmax tie band: exp(l-m) rounds to 1.0f when (m-l) <= 2^-25, so
    // argmax(softmax) picks the FIRST index inside that band.
    const float band = 2.9802322e-8f;  // 2^-25
    #pragma unroll 4
    for (int e = 0; e < NEXP; e++) {
        float4 c = sc[e];
        float dx = __fsub_rn(px, c.x);
        float dy = __fsub_rn(py, c.y);
        float dz = __fsub_rn(pz, c.z);
        float d2 = __fadd_rn(__fadd_rn(__fmul_rn(dx, dx), __fmul_rn(dy, dy)),
                             __fmul_rn(dz, dz));
        float dist = __fsqrt_rn(__fadd_rn(d2, 1e-12f));
        float li   = __fmul_rn(10.0f, __fsub_rn(c.w, dist));
        if (__fsub_rn(m, li) <= band) return e;
    }
    return NEXP - 1;  // unreachable
}

__global__ void __launch_bounds__(TPB)
optix_route_fused(const float* __restrict__ pos,
                  const float* __restrict__ centers,
                  const float* __restrict__ radii,
                  float* __restrict__ out_probs,
                  float* __restrict__ out_ids,
                  int B, int write_ids)
{
    __shared__ float4 sraw[NEXP];    // (cx, cy, cz, safe_r)  -- for exact path
    __shared__ float4 sdot[NEXP];    // (-2cx, -2cy, -2cz, |c|^2) -- fast path
    __shared__ int    sids[TPB];
    __shared__ int    s_uniform;
    __shared__ float  s_maxc2;

    const int tid = threadIdx.x;

    if (tid < NEXP) {
        float cx = centers[3 * tid + 0];
        float cy = centers[3 * tid + 1];
        float cz = centers[3 * tid + 2];
        float r  = fmaxf(fabsf(radii[tid]), 0.01f);
        sraw[tid] = make_float4(cx, cy, cz, r);
        float c2 = cx * cx + cy * cy + cz * cz;
        sdot[tid] = make_float4(-2.0f * cx, -2.0f * cy, -2.0f * cz, c2);
    }
    __syncthreads();
    if (tid == 0) {
        float r0 = sraw[0].w;
        int u = 1;
        float mc = 0.0f;
        #pragma unroll
        for (int e = 0; e < NEXP; e++) {
            u &= (sraw[e].w == r0);
            mc = fmaxf(mc, sdot[e].w);
        }
        s_uniform = u;
        s_maxc2   = mc;
    }
    __syncthreads();
    const int   uniform = s_uniform;
    const float maxc2   = s_maxc2;

    // ---- phase 1: argmax per row ----
    const long long gpos = (long long)blockIdx.x * TPB + tid;
    int id = 0;
    if (gpos < B) {
        const float px = pos[3 * gpos + 0];
        const float py = pos[3 * gpos + 1];
        const float pz = pos[3 * gpos + 2];

        // FAST PATH: uniform radii => logit order == reverse d2 order, and
        // d2 order == order of s = -2 p.c + |c|^2 (|p|^2 is row-constant).
        // 3 FMA per expert. Rounding deviation vs the reference's d2 is
        // absorbed by an absolute ambiguity margin scaled to the data.
        float best = FLT_MAX, best2 = FLT_MAX;
        #pragma unroll
        for (int e = 0; e < NEXP; e++) {
            float4 c = sdot[e];
            float s = __fmaf_rn(px, c.x, __fmaf_rn(py, c.y, __fmaf_rn(pz, c.z, c.w)));
            float mx = fmaxf(best, s);
            best2 = fminf(best2, mx);
            id    = (s < best) ? e : id;
            best  = fminf(best, s);
        }
        float pp  = __fmaf_rn(px, px, __fmaf_rn(py, py, pz * pz));
        float eps = 3e-5f * (pp + maxc2 + 1.0f);   // ~40x headroom over fp32 error
        bool need_exact = (!uniform) || (best2 - best <= eps);
        if (need_exact) id = exact_argmax(px, py, pz, sraw);
    }
    sids[tid] = id;
    __syncthreads();

    // ---- phase 2a: coalesced zero fill; tile is contiguous so address is
    // linear: outv[rowbase*16 + k*TPB + tid] ----
    const long long rowbase = (long long)blockIdx.x * TPB;
    float4* __restrict__ base = (float4*)out_probs + rowbase * 16 + tid;
    const float4 zero4 = make_float4(0.f, 0.f, 0.f, 0.f);
    if (rowbase + TPB <= B) {
        #pragma unroll
        for (int k = 0; k < 16; k++) base[k * TPB] = zero4;
    } else {
        #pragma unroll
        for (int k = 0; k < 16; k++) {
            long long idx = (long long)k * TPB + tid;
            if (rowbase + (idx >> 4) < B) base[k * TPB] = zero4;
        }
    }

    // orders the zero stores before the scatter within the block
    __syncthreads();

    // ---- phase 2b: scatter the hot 1.0f ----
    if (gpos < B) {
        out_probs[gpos * NEXP + id] = 1.0f;
        if (write_ids) out_ids[gpos] = (float)id;
    }
}

extern "C" void kernel_launch(void* const* d_in, const int* in_sizes, int n_in,
                              void* d_out, int out_size)
{
    const float* pos     = (const float*)d_in[0];   // positions_3d (B,3)
    const float* centers = (const float*)d_in[1];   // centers (64,3)
    const float* radii   = (const float*)d_in[2];   // radii (64,)

    int B = in_sizes[0] / 3;
    float* out_probs = (float*)d_out;
    long long need_ids = (long long)B * (NEXP + 1);
    int write_ids = ((long long)out_size >= need_ids) ? 1 : 0;
    float* out_ids = out_probs + (long long)B * NEXP;

    int grid = (B + TPB - 1) / TPB;
    optix_route_fused<<<grid, TPB>>>(pos, centers, radii, out_probs, out_ids, B, write_ids);
}

// round 7
// speedup vs baseline: 1.2441x; 1.2441x over previous
#include <cuda_runtime.h>
#include <cuda_bf16.h>
#include <float.h>

#define NEXP 64
#define TPB  256

// Rare exact path: faithful reproduction of the reference fp32 sequence
// (sqrt logits + softmax-tie band). __noinline__ + partial unroll so it never
// inflates the main kernel's register count (R3 lesson: inlining -> 255 regs).
__device__ __noinline__ int exact_argmax(float px, float py, float pz,
                                         const float4* __restrict__ sc)
{
    float m = -FLT_MAX;
    #pragma unroll 4
    for (int e = 0; e < NEXP; e++) {
        float4 c = sc[e];
        float dx = __fsub_rn(px, c.x);
        float dy = __fsub_rn(py, c.y);
        float dz = __fsub_rn(pz, c.z);
        float d2 = __fadd_rn(__fadd_rn(__fmul_rn(dx, dx), __fmul_rn(dy, dy)),
                             __fmul_rn(dz, dz));
        float dist = __fsqrt_rn(__fadd_rn(d2, 1e-12f));
        float li   = __fmul_rn(10.0f, __fsub_rn(c.w, dist));
        if (li > m) m = li;
    }
    // softmax tie band: exp(l-m) rounds to 1.0f when (m-l) <= 2^-25, so
    // argmax(softmax) picks the FIRST index inside that band.
    const float band = 2.9802322e-8f;  // 2^-25
    #pragma unroll 4
    for (int e = 0; e < NEXP; e++) {
        float4 c = sc[e];
        float dx = __fsub_rn(px, c.x);
        float dy = __fsub_rn(py, c.y);
        float dz = __fsub_rn(pz, c.z);
        float d2 = __fadd_rn(__fadd_rn(__fmul_rn(dx, dx), __fmul_rn(dy, dy)),
                             __fmul_rn(dz, dz));
        float dist = __fsqrt_rn(__fadd_rn(d2, 1e-12f));
        float li   = __fmul_rn(10.0f, __fsub_rn(c.w, dist));
        if (__fsub_rn(m, li) <= band) return e;
    }
    return NEXP - 1;  // unreachable
}

__global__ void __launch_bounds__(TPB)
optix_route_fused(const float* __restrict__ pos,
                  const float* __restrict__ centers,
                  const float* __restrict__ radii,
                  float* __restrict__ out_probs,
                  float* __restrict__ out_ids,
                  int B, int write_ids)
{
    __shared__ float4 sc[NEXP];      // (cx, cy, cz, safe_r)
    __shared__ int    sids[TPB];
    __shared__ int    s_uniform;

    const int tid = threadIdx.x;

    if (tid < NEXP) {
        float cx = centers[3 * tid + 0];
        float cy = centers[3 * tid + 1];
        float cz = centers[3 * tid + 2];
        float r  = fmaxf(fabsf(radii[tid]), 0.01f);
        sc[tid] = make_float4(cx, cy, cz, r);
    }
    __syncthreads();
    if (tid == 0) {
        float r0 = sc[0].w;
        int u = 1;
        #pragma unroll
        for (int e = 1; e < NEXP; e++) u &= (sc[e].w == r0);
        s_uniform = u;
    }
    __syncthreads();
    const int uniform = s_uniform;

    // ---- phase 1: argmax per row (R5's proven fast path) ----
    const long long gpos = (long long)blockIdx.x * TPB + tid;
    int id = 0;
    if (gpos < B) {
        const float px = pos[3 * gpos + 0];
        const float py = pos[3 * gpos + 1];
        const float pz = pos[3 * gpos + 2];

        bool need_exact = true;
        if (uniform) {
            // uniform radii => logit order == reverse d2 order. FMA-contracted
            // d2; <=~2.4e-7 relative deviation absorbed by the margin below.
            float best = FLT_MAX, best2 = FLT_MAX;
            #pragma unroll
            for (int e = 0; e < NEXP; e++) {
                float4 c = sc[e];
                float dx = px - c.x;
                float dy = py - c.y;
                float dz = pz - c.z;
                float d2 = __fmaf_rn(dx, dx, __fmaf_rn(dy, dy, dz * dz));
                float mx = fmaxf(best, d2);
                best2 = fminf(best2, mx);
                id    = (d2 < best) ? e : id;
                best  = fminf(best, d2);
            }
            need_exact = (best2 - best <= __fmaf_rn(best, 2e-6f, 1e-9f));
        }
        if (need_exact) id = exact_argmax(px, py, pz, sc);
    }
    sids[tid] = id;
    __syncthreads();

    // ---- phase 2: fused one-hot emission, one pass, no scatter ----
    // Element idx = k*256 + tid; since 256 % 16 == 0, the float4-column
    // c4 = tid & 15 is loop-invariant and row = k*16 + (tid>>4).
    // LDS + selects between STGs also paces the store stream (avoids the
    // front-batched-STG L1tex-queue contention that sank R6).
    const long long rowbase = (long long)blockIdx.x * TPB;
    float4* __restrict__ outv = (float4*)out_probs;
    const long long tilebase = rowbase * 16;          // float4 units
    const int c4b = (tid & 15) << 2;                  // first column of my quad
    const int rb  = tid >> 4;

    if (rowbase + TPB <= B) {
        #pragma unroll
        for (int k = 0; k < 16; k++) {
            int eid = sids[k * 16 + rb];
            int t = eid - c4b;
            float4 v;
            v.x = (t == 0) ? 1.0f : 0.0f;
            v.y = (t == 1) ? 1.0f : 0.0f;
            v.z = (t == 2) ? 1.0f : 0.0f;
            v.w = (t == 3) ? 1.0f : 0.0f;
            outv[tilebase + k * TPB + tid] = v;
        }
    } else {
        #pragma unroll
        for (int k = 0; k < 16; k++) {
            int row = k * 16 + rb;
            if (rowbase + row < B) {
                int eid = sids[row];
                int t = eid - c4b;
                float4 v;
                v.x = (t == 0) ? 1.0f : 0.0f;
                v.y = (t == 1) ? 1.0f : 0.0f;
                v.z = (t == 2) ? 1.0f : 0.0f;
                v.w = (t == 3) ? 1.0f : 0.0f;
                outv[tilebase + k * TPB + tid] = v;
            }
        }
    }

    if (write_ids && gpos < B) out_ids[gpos] = (float)id;
}

extern "C" void kernel_launch(void* const* d_in, const int* in_sizes, int n_in,
                              void* d_out, int out_size)
{
    const float* pos     = (const float*)d_in[0];   // positions_3d (B,3)
    const float* centers = (const float*)d_in[1];   // centers (64,3)
    const float* radii   = (const float*)d_in[2];   // radii (64,)

    int B = in_sizes[0] / 3;
    float* out_probs = (float*)d_out;
    long long need_ids = (long long)B * (NEXP + 1);
    int write_ids = ((long long)out_size >= need_ids) ? 1 : 0;
    float* out_ids = out_probs + (long long)B * NEXP;

    int grid = (B + TPB - 1) / TPB;
    optix_route_fused<<<grid, TPB>>>(pos, centers, radii, out_probs, out_ids, B, write_ids);
}